// round 1
// baseline (speedup 1.0000x reference)
#include <cuda_runtime.h>
#include <math.h>

#define N_REGIONS 10
#define HIDDEN    128
#define HEADS     4
#define N_LAYERS  3
#define CHPR      7
#define TOKENS    16384   // 16 * 1024

// neighbor lists: c_nbr[i][q] = j such that edge j->i exists (incl self loop)
__constant__ int c_nbr_cnt[N_REGIONS] = {5,5,5,3,3,4,3,4,2,2};
__constant__ int c_nbr[N_REGIONS][5] = {
    {0,1,2,3,4},    // prefrontal
    {0,1,2,5,7},    // broca
    {0,1,2,3,7},    // wernicke
    {0,2,3,0,0},    // visual
    {0,4,5,0,0},    // premotor
    {1,4,5,6,0},    // primary_motor
    {5,6,9,0,0},    // primary_sensory
    {1,2,7,8,0},    // auditory
    {7,8,0,0,0},    // auditory_assoc
    {6,9,0,0,0}     // somatic_sensory
};

__device__ __forceinline__ float gelu_exact(float v) {
    return 0.5f * v * (1.0f + erff(v * 0.70710678118654752f));
}

__global__ void __launch_bounds__(128, 8) brain_graph_kernel(
    const float* __restrict__ x,        // (16384, 70)
    const float* __restrict__ W_enc,    // (10, 7, 128)
    const float* __restrict__ b_enc,    // (10, 128)
    const float* __restrict__ g_enc,    // (10, 128)
    const float* __restrict__ beta_enc, // (10, 128)
    const float* __restrict__ W_gat,    // (3, 128, 4, 128)
    const float* __restrict__ att_src,  // (3, 4, 128)
    const float* __restrict__ att_dst,  // (3, 4, 128)
    const float* __restrict__ b_gat,    // (3, 128)
    float* __restrict__ out)            // [0,20971520) graph_features, [20971520,...) enc
{
    __shared__ float s_nodes[N_REGIONS][HIDDEN];        // 5120 B
    __shared__ float s_hh[N_REGIONS][HEADS * HIDDEN];   // 20480 B
    __shared__ float s_alpha[N_REGIONS][N_REGIONS][HEADS]; // 1600 B
    __shared__ float s_a[N_REGIONS][HEADS][2];          // [n][h][0]=a_src, [1]=a_dst
    __shared__ float s_x[CHPR * N_REGIONS];
    __shared__ float s_mu[N_REGIONS], s_rstd[N_REGIONS];

    const int tok  = blockIdx.x;
    const int t    = threadIdx.x;       // 0..127, = feature dim e
    const int wrp  = t >> 5;
    const int lane = t & 31;

    // ---- load token input ----
    if (t < CHPR * N_REGIONS) s_x[t] = x[(size_t)tok * (CHPR * N_REGIONS) + t];
    __syncthreads();

    // ---- region encoders: Linear(7,128) ----
    #pragma unroll
    for (int r = 0; r < N_REGIONS; r++) {
        float acc = b_enc[r * HIDDEN + t];
        #pragma unroll
        for (int c = 0; c < CHPR; c++)
            acc += s_x[r * CHPR + c] * W_enc[(r * CHPR + c) * HIDDEN + t];
        s_nodes[r][t] = acc;
    }
    __syncthreads();

    // ---- LayerNorm stats (per region, over 128 dims) ----
    for (int r = wrp; r < N_REGIONS; r += 4) {
        float v0 = s_nodes[r][lane];
        float v1 = s_nodes[r][lane + 32];
        float v2 = s_nodes[r][lane + 64];
        float v3 = s_nodes[r][lane + 96];
        float s  = v0 + v1 + v2 + v3;
        float sq = v0*v0 + v1*v1 + v2*v2 + v3*v3;
        #pragma unroll
        for (int o = 16; o > 0; o >>= 1) {
            s  += __shfl_xor_sync(0xffffffffu, s,  o);
            sq += __shfl_xor_sync(0xffffffffu, sq, o);
        }
        if (lane == 0) {
            float mu  = s * (1.0f / HIDDEN);
            float var = sq * (1.0f / HIDDEN) - mu * mu;
            s_mu[r]   = mu;
            s_rstd[r] = rsqrtf(var + 1e-5f);
        }
    }
    __syncthreads();

    // ---- LN affine + GELU; write enc output ----
    const size_t enc_base = (size_t)TOKENS * (N_REGIONS * HIDDEN) + (size_t)tok * (N_REGIONS * HIDDEN);
    #pragma unroll
    for (int r = 0; r < N_REGIONS; r++) {
        float v = (s_nodes[r][t] - s_mu[r]) * s_rstd[r] * g_enc[r * HIDDEN + t] + beta_enc[r * HIDDEN + t];
        float g = gelu_exact(v);
        s_nodes[r][t] = g;
        out[enc_base + r * HIDDEN + t] = g;
    }
    __syncthreads();

    // ---- GAT layers ----
    for (int l = 0; l < N_LAYERS; l++) {
        const float* Wg = W_gat + (size_t)l * (HIDDEN * HEADS * HIDDEN);

        // hh[n][o] = sum_k nodes[n][k] * Wg[k][o],  o = h*128 + e.
        // thread t handles o = t + 128*p (p=0..3): 1 LDG reused across 10 nodes.
        #pragma unroll
        for (int p = 0; p < HEADS; p++) {
            const int o = p * HIDDEN + t;
            const float* wp = Wg + o;
            float acc[N_REGIONS];
            #pragma unroll
            for (int n = 0; n < N_REGIONS; n++) acc[n] = 0.0f;
            #pragma unroll 4
            for (int k = 0; k < HIDDEN; k++) {
                float wv = __ldg(wp + (size_t)k * (HEADS * HIDDEN));
                #pragma unroll
                for (int n = 0; n < N_REGIONS; n++)
                    acc[n] += s_nodes[n][k] * wv;
            }
            #pragma unroll
            for (int n = 0; n < N_REGIONS; n++) s_hh[n][o] = acc[n];
        }
        __syncthreads();

        // attention scores a_s / a_d: 80 dot products of length 128, one per warp slot
        for (int idx = wrp; idx < N_REGIONS * HEADS * 2; idx += 4) {
            const int sd = idx & 1;
            const int h  = (idx >> 1) & 3;
            const int n  = idx >> 3;
            const float* att = (sd ? att_dst : att_src) + l * (HEADS * HIDDEN) + h * HIDDEN;
            float p = 0.0f;
            #pragma unroll
            for (int e = 0; e < HIDDEN; e += 32)
                p += s_hh[n][h * HIDDEN + e + lane] * att[e + lane];
            #pragma unroll
            for (int o = 16; o > 0; o >>= 1)
                p += __shfl_xor_sync(0xffffffffu, p, o);
            if (lane == 0) s_a[n][h][sd] = p;
        }
        __syncthreads();

        // softmax over neighbors: thread t < 40 handles (i,h)
        if (t < N_REGIONS * HEADS) {
            const int i = t >> 2, h = t & 3;
            const int cnt = c_nbr_cnt[i];
            const float ad = s_a[i][h][1];
            float lg[5];
            float mx = -1e30f;
            for (int q = 0; q < cnt; q++) {
                const int j = c_nbr[i][q];
                float v = ad + s_a[j][h][0];
                v = (v >= 0.0f) ? v : 0.2f * v;   // leaky relu 0.2
                lg[q] = v;
                mx = fmaxf(mx, v);
            }
            float sum = 0.0f;
            for (int q = 0; q < cnt; q++) { lg[q] = expf(lg[q] - mx); sum += lg[q]; }
            const float inv = 1.0f / sum;
            for (int q = 0; q < cnt; q++)
                s_alpha[i][c_nbr[i][q]][h] = lg[q] * inv;
        }
        __syncthreads();

        // aggregate + mean over heads + bias + GELU + residual
        const float bg = b_gat[l * HIDDEN + t];
        float newn[N_REGIONS];
        #pragma unroll
        for (int i = 0; i < N_REGIONS; i++) {
            float acc = 0.0f;
            const int cnt = c_nbr_cnt[i];
            for (int q = 0; q < cnt; q++) {
                const int j = c_nbr[i][q];
                #pragma unroll
                for (int h = 0; h < HEADS; h++)
                    acc += s_alpha[i][j][h] * s_hh[j][h * HIDDEN + t];
            }
            float v = acc * 0.25f + bg;
            newn[i] = gelu_exact(v) + s_nodes[i][t];
        }
        // each thread only touches its own column of s_nodes -> no cross-thread race
        #pragma unroll
        for (int i = 0; i < N_REGIONS; i++) s_nodes[i][t] = newn[i];
        __syncthreads();
    }

    // ---- graph_features output ----
    const size_t gf_base = (size_t)tok * (N_REGIONS * HIDDEN);
    #pragma unroll
    for (int i = 0; i < N_REGIONS; i++)
        out[gf_base + i * HIDDEN + t] = s_nodes[i][t];
}

extern "C" void kernel_launch(void* const* d_in, const int* in_sizes, int n_in,
                              void* d_out, int out_size) {
    (void)in_sizes; (void)n_in; (void)out_size;
    const float* x        = (const float*)d_in[0];
    const float* W_enc    = (const float*)d_in[1];
    const float* b_enc    = (const float*)d_in[2];
    const float* g_enc    = (const float*)d_in[3];
    const float* beta_enc = (const float*)d_in[4];
    const float* W_gat    = (const float*)d_in[5];
    const float* att_src  = (const float*)d_in[6];
    const float* att_dst  = (const float*)d_in[7];
    const float* b_gat    = (const float*)d_in[8];
    float* out = (float*)d_out;

    brain_graph_kernel<<<TOKENS, 128>>>(x, W_enc, b_enc, g_enc, beta_enc,
                                        W_gat, att_src, att_dst, b_gat, out);
}

// round 2
// speedup vs baseline: 1.2405x; 1.2405x over previous
#include <cuda_runtime.h>
#include <math.h>

#define N_REGIONS 10
#define HIDDEN    128
#define HEADS     4
#define N_LAYERS  3
#define CHPR      7
#define TOKENS    16384   // 16 * 1024
typedef unsigned long long u64;

// neighbor lists: c_nbr[i][q] = j such that edge j->i exists (incl self loop)
__constant__ int c_nbr_cnt[N_REGIONS] = {5,5,5,3,3,4,3,4,2,2};
__constant__ int c_nbr[N_REGIONS][5] = {
    {0,1,2,3,4},    // prefrontal
    {0,1,2,5,7},    // broca
    {0,1,2,3,7},    // wernicke
    {0,2,3,0,0},    // visual
    {0,4,5,0,0},    // premotor
    {1,4,5,6,0},    // primary_motor
    {5,6,9,0,0},    // primary_sensory
    {1,2,7,8,0},    // auditory
    {7,8,0,0,0},    // auditory_assoc
    {6,9,0,0,0}     // somatic_sensory
};

__device__ __forceinline__ float gelu_exact(float v) {
    return 0.5f * v * (1.0f + erff(v * 0.70710678118654752f));
}

// ---- packed f32x2 helpers (sm_103a) ----
__device__ __forceinline__ u64 pack2(float v) {
    u64 u; asm("mov.b64 %0, {%1,%2};" : "=l"(u) : "f"(v), "f"(v)); return u;
}
__device__ __forceinline__ u64 ffma2(u64 a, u64 b, u64 c) {  // a*b + c, elementwise
    u64 d; asm("fma.rn.f32x2 %0, %1, %2, %3;" : "=l"(d) : "l"(a), "l"(b), "l"(c)); return d;
}

__global__ void __launch_bounds__(128, 6) brain_graph_kernel(
    const float* __restrict__ x,        // (16384, 70)
    const float* __restrict__ W_enc,    // (10, 7, 128)
    const float* __restrict__ b_enc,    // (10, 128)
    const float* __restrict__ g_enc,    // (10, 128)
    const float* __restrict__ beta_enc, // (10, 128)
    const float* __restrict__ W_gat,    // (3, 128, 4, 128)
    const float* __restrict__ att_src,  // (3, 4, 128)
    const float* __restrict__ att_dst,  // (3, 4, 128)
    const float* __restrict__ b_gat,    // (3, 128)
    float* __restrict__ out)            // [0,20971520) graph_features, then enc
{
    // nodes stored DUPLICATED as {v,v} pairs so the GEMM does one LDS.64 per node per k
    __shared__ u64 s_nodes2[N_REGIONS][HIDDEN];            // 10 KB
    __shared__ u64 s_hh2[N_REGIONS][HEADS * HIDDEN / 2];   // 20 KB, float view = [n][512]
    __shared__ float s_alpha[N_REGIONS][N_REGIONS][HEADS]; // 1.6 KB
    __shared__ float s_a[N_REGIONS][HEADS][2];             // [n][h][0]=a_src, [1]=a_dst
    __shared__ float s_x[CHPR * N_REGIONS];
    __shared__ float s_mu[N_REGIONS], s_rstd[N_REGIONS];

    const int tok  = blockIdx.x;
    const int t    = threadIdx.x;       // 0..127
    const int wrp  = t >> 5;
    const int lane = t & 31;

    float* s_hh_f = (float*)s_hh2;      // [n][512] float view

    // ---- load token input ----
    if (t < CHPR * N_REGIONS) s_x[t] = x[(size_t)tok * (CHPR * N_REGIONS) + t];
    __syncthreads();

    // ---- region encoders: Linear(7,128) ----
    float encv[N_REGIONS];
    #pragma unroll
    for (int r = 0; r < N_REGIONS; r++) {
        float acc = b_enc[r * HIDDEN + t];
        #pragma unroll
        for (int c = 0; c < CHPR; c++)
            acc += s_x[r * CHPR + c] * W_enc[(r * CHPR + c) * HIDDEN + t];
        encv[r] = acc;
        s_nodes2[r][t] = pack2(acc);   // temp storage for LN stats
    }
    __syncthreads();

    // ---- LayerNorm stats (per region, over 128 dims) ----
    for (int r = wrp; r < N_REGIONS; r += 4) {
        const float* row = (const float*)&s_nodes2[r][0];   // stride-2 floats (dup pairs)
        float v0 = row[2 * lane];
        float v1 = row[2 * (lane + 32)];
        float v2 = row[2 * (lane + 64)];
        float v3 = row[2 * (lane + 96)];
        float s  = v0 + v1 + v2 + v3;
        float sq = v0*v0 + v1*v1 + v2*v2 + v3*v3;
        #pragma unroll
        for (int o = 16; o > 0; o >>= 1) {
            s  += __shfl_xor_sync(0xffffffffu, s,  o);
            sq += __shfl_xor_sync(0xffffffffu, sq, o);
        }
        if (lane == 0) {
            float mu  = s * (1.0f / HIDDEN);
            float var = sq * (1.0f / HIDDEN) - mu * mu;
            s_mu[r]   = mu;
            s_rstd[r] = rsqrtf(var + 1e-5f);
        }
    }
    __syncthreads();

    // ---- LN affine + GELU; write enc output ----
    const size_t enc_base = (size_t)TOKENS * (N_REGIONS * HIDDEN) + (size_t)tok * (N_REGIONS * HIDDEN);
    #pragma unroll
    for (int r = 0; r < N_REGIONS; r++) {
        float v = (encv[r] - s_mu[r]) * s_rstd[r] * g_enc[r * HIDDEN + t] + beta_enc[r * HIDDEN + t];
        float g = gelu_exact(v);
        s_nodes2[r][t] = pack2(g);
        out[enc_base + r * HIDDEN + t] = g;
    }
    __syncthreads();

    // ---- GAT layers ----
    for (int l = 0; l < N_LAYERS; l++) {
        // Weights viewed as pairs of adjacent output columns: W2[k][q], q=0..255
        const u64* __restrict__ W2 = (const u64*)(W_gat + (size_t)l * (HIDDEN * HEADS * HIDDEN));

        // hh[n][o] = sum_k nodes[n][k] * W[k][o]
        // thread t owns column pairs q0=t (o=2t,2t+1) and q1=t+128 (o=2t+256,2t+257)
        {
            u64 acc0[N_REGIONS], acc1[N_REGIONS];
            #pragma unroll
            for (int n = 0; n < N_REGIONS; n++) { acc0[n] = 0ull; acc1[n] = 0ull; }

            #pragma unroll 2
            for (int k = 0; k < HIDDEN; k++) {
                const u64 w0 = __ldg(W2 + (size_t)k * 256 + t);
                const u64 w1 = __ldg(W2 + (size_t)k * 256 + t + 128);
                #pragma unroll
                for (int n = 0; n < N_REGIONS; n++) {
                    const u64 nd = s_nodes2[n][k];   // broadcast LDS.64 of {v,v}
                    acc0[n] = ffma2(nd, w0, acc0[n]);
                    acc1[n] = ffma2(nd, w1, acc1[n]);
                }
            }
            #pragma unroll
            for (int n = 0; n < N_REGIONS; n++) {
                s_hh2[n][t]       = acc0[n];
                s_hh2[n][t + 128] = acc1[n];
            }
        }
        __syncthreads();

        // attention scores a_s / a_d: 80 dot products of length 128
        for (int idx = wrp; idx < N_REGIONS * HEADS * 2; idx += 4) {
            const int sd = idx & 1;
            const int h  = (idx >> 1) & 3;
            const int n  = idx >> 3;
            const float* att = (sd ? att_dst : att_src) + l * (HEADS * HIDDEN) + h * HIDDEN;
            float p = 0.0f;
            #pragma unroll
            for (int e = 0; e < HIDDEN; e += 32)
                p += s_hh_f[n * (HEADS * HIDDEN) + h * HIDDEN + e + lane] * att[e + lane];
            #pragma unroll
            for (int o = 16; o > 0; o >>= 1)
                p += __shfl_xor_sync(0xffffffffu, p, o);
            if (lane == 0) s_a[n][h][sd] = p;
        }
        __syncthreads();

        // softmax over neighbors: thread t < 40 handles (i,h)
        if (t < N_REGIONS * HEADS) {
            const int i = t >> 2, h = t & 3;
            const int cnt = c_nbr_cnt[i];
            const float ad = s_a[i][h][1];
            float lg[5];
            float mx = -1e30f;
            for (int q = 0; q < cnt; q++) {
                const int j = c_nbr[i][q];
                float v = ad + s_a[j][h][0];
                v = (v >= 0.0f) ? v : 0.2f * v;   // leaky relu 0.2
                lg[q] = v;
                mx = fmaxf(mx, v);
            }
            float sum = 0.0f;
            for (int q = 0; q < cnt; q++) { lg[q] = expf(lg[q] - mx); sum += lg[q]; }
            const float inv = 1.0f / sum;
            for (int q = 0; q < cnt; q++)
                s_alpha[i][c_nbr[i][q]][h] = lg[q] * inv;
        }
        __syncthreads();

        // aggregate + mean over heads + bias + GELU + residual
        const float bg = b_gat[l * HIDDEN + t];
        float newn[N_REGIONS];
        #pragma unroll
        for (int i = 0; i < N_REGIONS; i++) {
            float acc = 0.0f;
            const int cnt = c_nbr_cnt[i];
            for (int q = 0; q < cnt; q++) {
                const int j = c_nbr[i][q];
                #pragma unroll
                for (int h = 0; h < HEADS; h++)
                    acc += s_alpha[i][j][h] * s_hh_f[j * (HEADS * HIDDEN) + h * HIDDEN + t];
            }
            float v = acc * 0.25f + bg;
            const float prev = ((const float*)&s_nodes2[i][t])[0];
            newn[i] = gelu_exact(v) + prev;
        }
        __syncthreads();  // all reads of s_nodes2 done before overwrite
        #pragma unroll
        for (int i = 0; i < N_REGIONS; i++) s_nodes2[i][t] = pack2(newn[i]);
        __syncthreads();
    }

    // ---- graph_features output ----
    const size_t gf_base = (size_t)tok * (N_REGIONS * HIDDEN);
    #pragma unroll
    for (int i = 0; i < N_REGIONS; i++)
        out[gf_base + i * HIDDEN + t] = ((const float*)&s_nodes2[i][t])[0];
}

extern "C" void kernel_launch(void* const* d_in, const int* in_sizes, int n_in,
                              void* d_out, int out_size) {
    (void)in_sizes; (void)n_in; (void)out_size;
    const float* x        = (const float*)d_in[0];
    const float* W_enc    = (const float*)d_in[1];
    const float* b_enc    = (const float*)d_in[2];
    const float* g_enc    = (const float*)d_in[3];
    const float* beta_enc = (const float*)d_in[4];
    const float* W_gat    = (const float*)d_in[5];
    const float* att_src  = (const float*)d_in[6];
    const float* att_dst  = (const float*)d_in[7];
    const float* b_gat    = (const float*)d_in[8];
    float* out = (float*)d_out;

    brain_graph_kernel<<<TOKENS, 128>>>(x, W_enc, b_enc, g_enc, beta_enc,
                                        W_gat, att_src, att_dst, b_gat, out);
}